// round 11
// baseline (speedup 1.0000x reference)
#include <cuda_runtime.h>
#include <math.h>

#define NB  8
#define H   12
#define DH  64
#define LV  1568
#define LA  512
#define NCV 392
#define NCA 256
#define ROW 5696
#define OFF_PROBV 0
#define OFF_PROBA 1568
#define OFF_VCLS  2080
#define OFF_ACLS  2848
#define OFF_PRAV  3616
#define OFF_PRVA  5184

// ---------- scratch ----------
__device__ int   g_cidx_v[NB * NCV];
__device__ float g_w_v[NB * NCV];
__device__ int   g_cidx_a[NB * NCA];
__device__ float g_w_a[NB * NCA];
__device__ float g_invS_av[NB];
__device__ float g_invS_va[NB];
__device__ float g_probv[NB * NCV];
__device__ float g_proba[NB * NCA];
__device__ float g_vpos[NB * H * NCV];   // v-side pos numerators (per n,h,slot)

// ---------- kernel 1: compaction (sides 0/1) + output default fill (sides 2/3) ----------
// grid (NB, 4)
__global__ void kprep(const float* __restrict__ n_attn_av,
                      const float* __restrict__ n_attn_va,
                      const int* __restrict__ ids_v,
                      const int* __restrict__ ids_a,
                      float* __restrict__ out) {
    int n = blockIdx.x, side = blockIdx.y, tid = threadIdx.x;

    if (side >= 2) {
        float* row = out + (size_t)n * ROW;
        if (side == 2) {
            for (int j = tid; j < LV; j += 512) {
                row[OFF_PROBV + j] = 0.f;
                row[OFF_PRAV + j]  = n_attn_av[n * LV + j];
            }
        } else {
            for (int j = tid; j < LA; j += 512) {
                row[OFF_PROBA + j] = 0.f;
                row[OFF_PRVA + j]  = n_attn_va[n * LA + j];
            }
        }
        return;
    }

    int lane = tid & 31, wrp = tid >> 5;
    __shared__ int   s_rank[LV];
    __shared__ int   s_wsum[16];
    __shared__ float s_red[512];

    int full = side ? LA : LV;
    int cnt  = side ? NCA : NCV;
    const int*   ids = side ? ids_a : ids_v;
    const float* na  = side ? n_attn_va : n_attn_av;

    for (int t = tid; t < full; t += 512) s_rank[ids[n * full + t]] = t;
    if (side) {
        if (tid < NCA) g_proba[n * NCA + tid] = 0.f;
    } else {
        if (tid < NCV) g_probv[n * NCV + tid] = 0.f;
        for (int t = tid; t < H * NCV; t += 512) g_vpos[n * H * NCV + t] = 0.f;
    }
    __syncthreads();

    int per = (full + 511) >> 9;
    int base = tid * per;
    int keep[4]; int k = 0; float ws = 0.f;
    for (int i = 0; i < per; i++) {
        int j = base + i;
        if (j < full && s_rank[j] < cnt) { keep[k++] = j; ws += na[n * full + j]; }
    }
    int inc = k;
    for (int d = 1; d < 32; d <<= 1) {
        int v = __shfl_up_sync(0xffffffffu, inc, d);
        if (lane >= d) inc += v;
    }
    if (lane == 31) s_wsum[wrp] = inc;
    __syncthreads();
    if (wrp == 0 && lane < 16) {
        int v = s_wsum[lane];
        for (int d = 1; d < 16; d <<= 1) {
            int u = __shfl_up_sync(0xffffu, v, d);
            if (lane >= d) v += u;
        }
        s_wsum[lane] = v;
    }
    __syncthreads();
    int off = (wrp ? s_wsum[wrp - 1] : 0) + inc - k;
    for (int i = 0; i < k; i++) {
        int j = keep[i];
        int slot = off + i;
        if (side) { g_cidx_a[n * NCA + slot] = j; g_w_a[n * NCA + slot] = na[n * LA + j]; }
        else      { g_cidx_v[n * NCV + slot] = j; g_w_v[n * NCV + slot] = na[n * LV + j]; }
    }
    s_red[tid] = ws;
    __syncthreads();
    for (int s = 256; s > 0; s >>= 1) {
        if (tid < s) s_red[tid] += s_red[tid + s];
        __syncthreads();
    }
    if (tid == 0) {
        if (side) g_invS_va[n] = 1.f / s_red[0];
        else      g_invS_av[n] = 1.f / s_red[0];
    }
}

// ---------- kernel 2: balanced main ----------
// grid (H, NB, 3):
//   z==0: v side, a-rows [0,128)   + v cls
//   z==1: v side, a-rows [128,256)
//   z==2: a side, full (fused sigmoid + a cls), exact round-7 path
__global__ void __launch_bounds__(512, 2)
kmain(const float* __restrict__ pos_v_q, const float* __restrict__ pos_v_k,
      const float* __restrict__ pos_a_q, const float* __restrict__ pos_a_k,
      const float* __restrict__ M_av,    const float* __restrict__ M_va,
      const float* __restrict__ spu_a_cls, const float* __restrict__ spu_v_cls,
      float* __restrict__ out) {
    int h = blockIdx.x, n = blockIdx.y, z = blockIdx.z;
    int tid = threadIdx.x;

    __shared__ int   s_idxL[NCV];
    __shared__ float s_wL[NCV];
    __shared__ int   s_offS[NCV];
    __shared__ float s_wS[NCV];
    __shared__ float s_cls[DH];
    __shared__ float s_red[512];

    if (z < 2) {
        // ---- v side, S-chunk of 128 a-rows ----
        int r0 = z * 128;
        if (tid < NCV) {
            s_idxL[tid] = g_cidx_v[n * NCV + tid];
            s_wL[tid]   = g_w_v[n * NCV + tid];
        }
        if (tid < 128) {
            s_offS[tid] = g_cidx_a[n * NCA + r0 + tid] * LV;
            s_wS[tid]   = g_w_a[n * NCA + r0 + tid];
        }
        __syncthreads();

        const float* Mbase = M_av + (size_t)(n * H + h) * (size_t)LA * LV;
        if (tid < NCV) {
            int il = s_idxL[tid];
            float p0 = 0.f, p1 = 0.f, p2 = 0.f, p3 = 0.f;
            for (int a = 0; a < 128; a += 4) {
                p0 = fmaf(Mbase[s_offS[a + 0] + il], s_wS[a + 0], p0);
                p1 = fmaf(Mbase[s_offS[a + 1] + il], s_wS[a + 1], p1);
                p2 = fmaf(Mbase[s_offS[a + 2] + il], s_wS[a + 2], p2);
                p3 = fmaf(Mbase[s_offS[a + 3] + il], s_wS[a + 3], p3);
            }
            atomicAdd(&g_vpos[(size_t)(n * H + h) * NCV + tid],
                      (p0 + p1) + (p2 + p3));
        }

        if (z == 0) {
            // v cls: weighted sum of gathered q rows
            const float* qbase = pos_v_q + (size_t)(n * H + h) * LV * DH;
            int g = tid >> 6, d = tid & 63;
            float a2 = 0.f;
            for (int l = g; l < NCV; l += 8)
                a2 = fmaf(qbase[(size_t)s_idxL[l] * DH + d], s_wL[l], a2);
            s_red[tid] = a2;
            __syncthreads();
            if (tid < DH) {
                float t = 0.f;
                #pragma unroll
                for (int gg = 0; gg < 8; gg++) t += s_red[gg * 64 + tid];
                out[(size_t)n * ROW + OFF_VCLS + h * DH + tid] = t * g_invS_av[n];
            }
        }
        return;
    }

    // ---- a side: exact round-7 fused path ----
    float invS_pos = g_invS_av[n], invS_cls = g_invS_va[n];
    float* acc = g_proba + n * NCA;

    if (tid < NCA) {
        s_idxL[tid] = g_cidx_a[n * NCA + tid];
        s_wL[tid]   = g_w_a[n * NCA + tid];
    }
    if (tid < NCV) {
        s_offS[tid] = g_cidx_v[n * NCV + tid] * LA;
        s_wS[tid]   = g_w_v[n * NCV + tid];
    }
    if (tid < DH) s_cls[tid] = spu_v_cls[(n * H + h) * DH + tid];
    __syncthreads();

    const float* kbase = pos_a_k + (size_t)(n * H + h) * LA * DH;
    const float* Mbase = M_va + (size_t)(n * H + h) * (size_t)LV * LA;

    if (tid < NCA) {
        int il = s_idxL[tid];
        const float4* krow = (const float4*)(kbase + (size_t)il * DH);
        float spu = 0.f;
        #pragma unroll
        for (int d4 = 0; d4 < DH / 4; d4++) {
            float4 v = krow[d4];
            spu = fmaf(v.x, s_cls[4 * d4 + 0], spu);
            spu = fmaf(v.y, s_cls[4 * d4 + 1], spu);
            spu = fmaf(v.z, s_cls[4 * d4 + 2], spu);
            spu = fmaf(v.w, s_cls[4 * d4 + 3], spu);
        }
        spu *= 0.125f;
        float p0 = 0.f, p1 = 0.f, p2 = 0.f, p3 = 0.f;
        for (int a = 0; a < NCV; a += 4) {
            p0 = fmaf(Mbase[s_offS[a + 0] + il], s_wS[a + 0], p0);
            p1 = fmaf(Mbase[s_offS[a + 1] + il], s_wS[a + 1], p1);
            p2 = fmaf(Mbase[s_offS[a + 2] + il], s_wS[a + 2], p2);
            p3 = fmaf(Mbase[s_offS[a + 3] + il], s_wS[a + 3], p3);
        }
        float posv = ((p0 + p1) + (p2 + p3)) * invS_pos;
        float sig = 1.f / (1.f + __expf(posv - spu));
        atomicAdd(&acc[tid], sig);
    }

    const float* qbase = pos_a_q + (size_t)(n * H + h) * LA * DH;
    {
        int g = tid >> 6, d = tid & 63;
        float a2 = 0.f;
        for (int l = g; l < NCA; l += 8)
            a2 = fmaf(qbase[(size_t)s_idxL[l] * DH + d], s_wL[l], a2);
        s_red[tid] = a2;
        __syncthreads();
        if (tid < DH) {
            float t = 0.f;
            #pragma unroll
            for (int gg = 0; gg < 8; gg++) t += s_red[gg * 64 + tid];
            out[(size_t)n * ROW + OFF_ACLS + h * DH + tid] = t * invS_cls;
        }
    }
}

// ---------- kernel 3: v-side spu + sigmoid; grid (H, NB) ----------
__global__ void __launch_bounds__(512, 2)
ksig(const float* __restrict__ pos_v_k,
     const float* __restrict__ spu_a_cls) {
    int h = blockIdx.x, n = blockIdx.y, tid = threadIdx.x;
    __shared__ float s_cls[DH];
    if (tid < DH) s_cls[tid] = spu_a_cls[(n * H + h) * DH + tid];
    __syncthreads();

    if (tid < NCV) {
        int il = g_cidx_v[n * NCV + tid];
        const float4* krow = (const float4*)(pos_v_k + (size_t)(n * H + h) * LV * DH
                                             + (size_t)il * DH);
        float spu = 0.f;
        #pragma unroll
        for (int d4 = 0; d4 < DH / 4; d4++) {
            float4 v = krow[d4];
            spu = fmaf(v.x, s_cls[4 * d4 + 0], spu);
            spu = fmaf(v.y, s_cls[4 * d4 + 1], spu);
            spu = fmaf(v.z, s_cls[4 * d4 + 2], spu);
            spu = fmaf(v.w, s_cls[4 * d4 + 3], spu);
        }
        spu *= 0.125f;
        float posv = g_vpos[(size_t)(n * H + h) * NCV + tid] * g_invS_va[n];
        float sig = 1.f / (1.f + __expf(posv - spu));
        atomicAdd(&g_probv[n * NCV + tid], sig);
    }
}

// ---------- kernel 4: scatter + prune; grid (NB, 2) ----------
__global__ void kfin(const float* __restrict__ n_attn_av,
                     const float* __restrict__ n_attn_va,
                     const float* __restrict__ u_v,
                     const float* __restrict__ u_a,
                     float* __restrict__ out) {
    int n = blockIdx.x, side = blockIdx.y, tid = threadIdx.x;
    float* row = out + (size_t)n * ROW;
    if (side == 0) {
        if (tid < NCV) {
            int pos = g_cidx_v[n * NCV + tid];
            float p = g_probv[n * NCV + tid] * (1.f / 12.f);
            row[OFF_PROBV + pos] = p;
            row[OFF_PRAV + pos]  = (u_v[n * LV + pos] < p) ? 0.f : n_attn_av[n * LV + pos];
        }
    } else {
        if (tid < NCA) {
            int pos = g_cidx_a[n * NCA + tid];
            float p = g_proba[n * NCA + tid] * (1.f / 12.f);
            row[OFF_PROBA + pos] = p;
            row[OFF_PRVA + pos]  = (u_a[n * LA + pos] < p) ? 0.f : n_attn_va[n * LA + pos];
        }
    }
}

extern "C" void kernel_launch(void* const* d_in, const int* in_sizes, int n_in,
                              void* d_out, int out_size) {
    const float* pos_v_q   = (const float*)d_in[0];
    const float* pos_v_k   = (const float*)d_in[1];
    const float* pos_a_q   = (const float*)d_in[2];
    const float* pos_a_k   = (const float*)d_in[3];
    const float* M_av      = (const float*)d_in[4];
    const float* M_va      = (const float*)d_in[5];
    const float* n_attn_av = (const float*)d_in[6];
    const float* n_attn_va = (const float*)d_in[7];
    const float* spu_a_cls = (const float*)d_in[8];
    const float* spu_v_cls = (const float*)d_in[9];
    const float* u_v       = (const float*)d_in[10];
    const float* u_a       = (const float*)d_in[11];
    const int*   ids_v     = (const int*)d_in[12];
    const int*   ids_a     = (const int*)d_in[13];
    float* out = (float*)d_out;

    kprep<<<dim3(NB, 4), 512>>>(n_attn_av, n_attn_va, ids_v, ids_a, out);
    kmain<<<dim3(H, NB, 3), 512>>>(pos_v_q, pos_v_k, pos_a_q, pos_a_k,
                                   M_av, M_va, spu_a_cls, spu_v_cls, out);
    ksig<<<dim3(H, NB), 512>>>(pos_v_k, spu_a_cls);
    kfin<<<dim3(NB, 2), 512>>>(n_attn_av, n_attn_va, u_v, u_a, out);
}

// round 12
// speedup vs baseline: 1.2340x; 1.2340x over previous
#include <cuda_runtime.h>
#include <math.h>

#define NB  8
#define H   12
#define DH  64
#define LV  1568
#define LA  512
#define NCV 392
#define NCA 256
#define ROW 5696
#define OFF_PROBV 0
#define OFF_PROBA 1568
#define OFF_VCLS  2080
#define OFF_ACLS  2848
#define OFF_PRAV  3616
#define OFF_PRVA  5184

// ---------- scratch ----------
__device__ int   g_cidx_v[NB * NCV];   // sorted gathered v-token ids
__device__ float g_w_v[NB * NCV];
__device__ int   g_cidx_a[NB * NCA];
__device__ float g_w_a[NB * NCA];
__device__ float g_invS_av[NB];
__device__ float g_invS_va[NB];
__device__ float g_probv[NB * NCV];
__device__ float g_proba[NB * NCA];

// ---------- kernel 1: compaction (sides 0/1) + output default fill (sides 2/3) ----------
// grid (NB, 4)  [identical to round-10]
__global__ void kprep(const float* __restrict__ n_attn_av,
                      const float* __restrict__ n_attn_va,
                      const int* __restrict__ ids_v,
                      const int* __restrict__ ids_a,
                      float* __restrict__ out) {
    int n = blockIdx.x, side = blockIdx.y, tid = threadIdx.x;

    if (side >= 2) {
        float* row = out + (size_t)n * ROW;
        if (side == 2) {
            for (int j = tid; j < LV; j += 512) {
                row[OFF_PROBV + j] = 0.f;
                row[OFF_PRAV + j]  = n_attn_av[n * LV + j];
            }
        } else {
            for (int j = tid; j < LA; j += 512) {
                row[OFF_PROBA + j] = 0.f;
                row[OFF_PRVA + j]  = n_attn_va[n * LA + j];
            }
        }
        return;
    }

    int lane = tid & 31, wrp = tid >> 5;
    __shared__ int   s_rank[LV];
    __shared__ int   s_wsum[16];
    __shared__ float s_red[512];

    int full = side ? LA : LV;
    int cnt  = side ? NCA : NCV;
    const int*   ids = side ? ids_a : ids_v;
    const float* na  = side ? n_attn_va : n_attn_av;

    for (int t = tid; t < full; t += 512) s_rank[ids[n * full + t]] = t;
    if (side) { if (tid < NCA) g_proba[n * NCA + tid] = 0.f; }
    else      { if (tid < NCV) g_probv[n * NCV + tid] = 0.f; }
    __syncthreads();

    int per = (full + 511) >> 9;
    int base = tid * per;
    int keep[4]; int k = 0; float ws = 0.f;
    for (int i = 0; i < per; i++) {
        int j = base + i;
        if (j < full && s_rank[j] < cnt) { keep[k++] = j; ws += na[n * full + j]; }
    }
    int inc = k;
    for (int d = 1; d < 32; d <<= 1) {
        int v = __shfl_up_sync(0xffffffffu, inc, d);
        if (lane >= d) inc += v;
    }
    if (lane == 31) s_wsum[wrp] = inc;
    __syncthreads();
    if (wrp == 0 && lane < 16) {
        int v = s_wsum[lane];
        for (int d = 1; d < 16; d <<= 1) {
            int u = __shfl_up_sync(0xffffu, v, d);
            if (lane >= d) v += u;
        }
        s_wsum[lane] = v;
    }
    __syncthreads();
    int off = (wrp ? s_wsum[wrp - 1] : 0) + inc - k;
    for (int i = 0; i < k; i++) {
        int j = keep[i];
        int slot = off + i;
        if (side) { g_cidx_a[n * NCA + slot] = j; g_w_a[n * NCA + slot] = na[n * LA + j]; }
        else      { g_cidx_v[n * NCV + slot] = j; g_w_v[n * NCV + slot] = na[n * LV + j]; }
    }
    s_red[tid] = ws;
    __syncthreads();
    for (int s = 256; s > 0; s >>= 1) {
        if (tid < s) s_red[tid] += s_red[tid + s];
        __syncthreads();
    }
    if (tid == 0) {
        if (side) g_invS_va[n] = 1.f / s_red[0];
        else      g_invS_av[n] = 1.f / s_red[0];
    }
}

// ---------- kernel 2: round-10 kmain, LINEAR grid with skew-free bid map ----------
// 192 blocks. bid%148 collisions pair (bid, bid+148) on one SM -> make those a+a.
//   bid [0,44)    : a-side
//   bid [44,140)  : v-side (96)
//   bid [140,148) : a-side
//   bid [148,192) : a-side  (pairs with bids 0..43 -> a+a SMs, 1.6MB max)
__global__ void __launch_bounds__(512, 2)
kmain(const float* __restrict__ pos_v_q, const float* __restrict__ pos_v_k,
      const float* __restrict__ pos_a_q, const float* __restrict__ pos_a_k,
      const float* __restrict__ M_av,    const float* __restrict__ M_va,
      const float* __restrict__ spu_a_cls, const float* __restrict__ spu_v_cls,
      float* __restrict__ out) {
    int bid = blockIdx.x;
    int side, idx;
    if (bid < 44)       { side = 1; idx = bid; }
    else if (bid < 140) { side = 0; idx = bid - 44; }
    else if (bid < 148) { side = 1; idx = 44 + (bid - 140); }
    else                { side = 1; idx = 52 + (bid - 148); }
    int h = idx % H, n = idx / H;
    int tid = threadIdx.x;

    __shared__ int   s_idxL[NCV];
    __shared__ float s_wL[NCV];
    __shared__ int   s_offS[NCV];
    __shared__ float s_wS[NCV];
    __shared__ float s_cls[DH];
    __shared__ float s_red[512];

    int Lcnt, Scnt, Mstride, clsoff;
    const float *kten, *qten, *M, *cls;
    const int *cidxL, *cidxS;
    const float *gwL, *gwS;
    float invS_pos, invS_cls;
    float* acc;
    if (side == 0) {
        Lcnt = NCV; Scnt = NCA; Mstride = LV; clsoff = OFF_VCLS;
        kten = pos_v_k; qten = pos_v_q; M = M_av; cls = spu_a_cls;
        cidxL = g_cidx_v; cidxS = g_cidx_a;
        gwL = g_w_v; gwS = g_w_a;
        invS_pos = g_invS_va[n]; invS_cls = g_invS_av[n];
        acc = g_probv + n * NCV;
    } else {
        Lcnt = NCA; Scnt = NCV; Mstride = LA; clsoff = OFF_ACLS;
        kten = pos_a_k; qten = pos_a_q; M = M_va; cls = spu_v_cls;
        cidxL = g_cidx_a; cidxS = g_cidx_v;
        gwL = g_w_a; gwS = g_w_v;
        invS_pos = g_invS_av[n]; invS_cls = g_invS_va[n];
        acc = g_proba + n * NCA;
    }

    if (tid < Lcnt) {
        s_idxL[tid] = cidxL[n * Lcnt + tid];
        s_wL[tid]   = gwL[n * Lcnt + tid];
    }
    if (tid < Scnt) {
        s_offS[tid] = cidxS[n * Scnt + tid] * Mstride;
        s_wS[tid]   = gwS[n * Scnt + tid];
    }
    if (tid < DH) s_cls[tid] = cls[(n * H + h) * DH + tid];
    __syncthreads();

    const float* kbase = kten + (size_t)(n * H + h) * (side ? LA : LV) * DH;
    const float* Mbase = M + (size_t)(n * H + h) * (size_t)LA * LV;

    if (tid < Lcnt) {
        int il = s_idxL[tid];
        const float4* krow = (const float4*)(kbase + (size_t)il * DH);
        float spu = 0.f;
        #pragma unroll
        for (int d4 = 0; d4 < DH / 4; d4++) {
            float4 v = krow[d4];
            spu = fmaf(v.x, s_cls[4 * d4 + 0], spu);
            spu = fmaf(v.y, s_cls[4 * d4 + 1], spu);
            spu = fmaf(v.z, s_cls[4 * d4 + 2], spu);
            spu = fmaf(v.w, s_cls[4 * d4 + 3], spu);
        }
        spu *= 0.125f;
        float p0 = 0.f, p1 = 0.f, p2 = 0.f, p3 = 0.f;
        for (int a = 0; a < Scnt; a += 4) {
            p0 = fmaf(Mbase[s_offS[a + 0] + il], s_wS[a + 0], p0);
            p1 = fmaf(Mbase[s_offS[a + 1] + il], s_wS[a + 1], p1);
            p2 = fmaf(Mbase[s_offS[a + 2] + il], s_wS[a + 2], p2);
            p3 = fmaf(Mbase[s_offS[a + 3] + il], s_wS[a + 3], p3);
        }
        float posv = ((p0 + p1) + (p2 + p3)) * invS_pos;
        float sig = 1.f / (1.f + __expf(posv - spu));
        atomicAdd(&acc[tid], sig);
    }

    // cls: weighted sum of gathered q rows -> 64 floats, direct store
    const float* qbase = qten + (size_t)(n * H + h) * (side ? LA : LV) * DH;
    {
        int g = tid >> 6, d = tid & 63;
        float a2 = 0.f;
        for (int l = g; l < Lcnt; l += 8)
            a2 = fmaf(qbase[(size_t)s_idxL[l] * DH + d], s_wL[l], a2);
        s_red[tid] = a2;
        __syncthreads();
        if (tid < DH) {
            float t = 0.f;
            #pragma unroll
            for (int gg = 0; gg < 8; gg++) t += s_red[gg * 64 + tid];
            out[(size_t)n * ROW + clsoff + h * DH + tid] = t * invS_cls;
        }
    }
}

// ---------- kernel 3: scatter + prune only; grid (NB, 2)  [identical to round-10] ----------
__global__ void kfin(const float* __restrict__ n_attn_av,
                     const float* __restrict__ n_attn_va,
                     const float* __restrict__ u_v,
                     const float* __restrict__ u_a,
                     float* __restrict__ out) {
    int n = blockIdx.x, side = blockIdx.y, tid = threadIdx.x;
    float* row = out + (size_t)n * ROW;
    if (side == 0) {
        if (tid < NCV) {
            int pos = g_cidx_v[n * NCV + tid];
            float p = g_probv[n * NCV + tid] * (1.f / 12.f);
            row[OFF_PROBV + pos] = p;
            row[OFF_PRAV + pos]  = (u_v[n * LV + pos] < p) ? 0.f : n_attn_av[n * LV + pos];
        }
    } else {
        if (tid < NCA) {
            int pos = g_cidx_a[n * NCA + tid];
            float p = g_proba[n * NCA + tid] * (1.f / 12.f);
            row[OFF_PROBA + pos] = p;
            row[OFF_PRVA + pos]  = (u_a[n * LA + pos] < p) ? 0.f : n_attn_va[n * LA + pos];
        }
    }
}

extern "C" void kernel_launch(void* const* d_in, const int* in_sizes, int n_in,
                              void* d_out, int out_size) {
    const float* pos_v_q   = (const float*)d_in[0];
    const float* pos_v_k   = (const float*)d_in[1];
    const float* pos_a_q   = (const float*)d_in[2];
    const float* pos_a_k   = (const float*)d_in[3];
    const float* M_av      = (const float*)d_in[4];
    const float* M_va      = (const float*)d_in[5];
    const float* n_attn_av = (const float*)d_in[6];
    const float* n_attn_va = (const float*)d_in[7];
    const float* spu_a_cls = (const float*)d_in[8];
    const float* spu_v_cls = (const float*)d_in[9];
    const float* u_v       = (const float*)d_in[10];
    const float* u_a       = (const float*)d_in[11];
    const int*   ids_v     = (const int*)d_in[12];
    const int*   ids_a     = (const int*)d_in[13];
    float* out = (float*)d_out;

    kprep<<<dim3(NB, 4), 512>>>(n_attn_av, n_attn_va, ids_v, ids_a, out);
    kmain<<<192, 512>>>(pos_v_q, pos_v_k, pos_a_q, pos_a_k,
                        M_av, M_va, spu_a_cls, spu_v_cls, out);
    kfin<<<dim3(NB, 2), 512>>>(n_attn_av, n_attn_va, u_v, u_a, out);
}

// round 13
// speedup vs baseline: 1.2832x; 1.0398x over previous
#include <cuda_runtime.h>
#include <math.h>

#define NB  8
#define H   12
#define DH  64
#define LV  1568
#define LA  512
#define NCV 392
#define NCA 256
#define ROW 5696
#define OFF_PROBV 0
#define OFF_PROBA 1568
#define OFF_VCLS  2080
#define OFF_ACLS  2848
#define OFF_PRAV  3616
#define OFF_PRVA  5184

// ---------- scratch ----------
__device__ int   g_cidx_v[NB * NCV];   // sorted gathered v-token ids
__device__ float g_w_v[NB * NCV];
__device__ int   g_cidx_a[NB * NCA];
__device__ float g_w_a[NB * NCA];
__device__ float g_invS_av[NB];
__device__ float g_invS_va[NB];
__device__ float g_probv[NB * NCV];
__device__ float g_proba[NB * NCA];
__device__ int   g_cnt[NB * 2];        // per-(n,side) completion counters

// ---------- kernel 1: compaction (sides 0/1) + output default fill (sides 2/3) ----------
// grid (NB, 4)  [identical to round-10, + counter reset]
__global__ void kprep(const float* __restrict__ n_attn_av,
                      const float* __restrict__ n_attn_va,
                      const int* __restrict__ ids_v,
                      const int* __restrict__ ids_a,
                      float* __restrict__ out) {
    int n = blockIdx.x, side = blockIdx.y, tid = threadIdx.x;

    if (side >= 2) {
        float* row = out + (size_t)n * ROW;
        if (side == 2) {
            for (int j = tid; j < LV; j += 512) {
                row[OFF_PROBV + j] = 0.f;
                row[OFF_PRAV + j]  = n_attn_av[n * LV + j];
            }
        } else {
            for (int j = tid; j < LA; j += 512) {
                row[OFF_PROBA + j] = 0.f;
                row[OFF_PRVA + j]  = n_attn_va[n * LA + j];
            }
        }
        return;
    }

    int lane = tid & 31, wrp = tid >> 5;
    __shared__ int   s_rank[LV];
    __shared__ int   s_wsum[16];
    __shared__ float s_red[512];

    int full = side ? LA : LV;
    int cnt  = side ? NCA : NCV;
    const int*   ids = side ? ids_a : ids_v;
    const float* na  = side ? n_attn_va : n_attn_av;

    if (tid == 0) g_cnt[n * 2 + side] = 0;      // reset completion counter
    for (int t = tid; t < full; t += 512) s_rank[ids[n * full + t]] = t;
    if (side) { if (tid < NCA) g_proba[n * NCA + tid] = 0.f; }
    else      { if (tid < NCV) g_probv[n * NCV + tid] = 0.f; }
    __syncthreads();

    int per = (full + 511) >> 9;
    int base = tid * per;
    int keep[4]; int k = 0; float ws = 0.f;
    for (int i = 0; i < per; i++) {
        int j = base + i;
        if (j < full && s_rank[j] < cnt) { keep[k++] = j; ws += na[n * full + j]; }
    }
    int inc = k;
    for (int d = 1; d < 32; d <<= 1) {
        int v = __shfl_up_sync(0xffffffffu, inc, d);
        if (lane >= d) inc += v;
    }
    if (lane == 31) s_wsum[wrp] = inc;
    __syncthreads();
    if (wrp == 0 && lane < 16) {
        int v = s_wsum[lane];
        for (int d = 1; d < 16; d <<= 1) {
            int u = __shfl_up_sync(0xffffu, v, d);
            if (lane >= d) v += u;
        }
        s_wsum[lane] = v;
    }
    __syncthreads();
    int off = (wrp ? s_wsum[wrp - 1] : 0) + inc - k;
    for (int i = 0; i < k; i++) {
        int j = keep[i];
        int slot = off + i;
        if (side) { g_cidx_a[n * NCA + slot] = j; g_w_a[n * NCA + slot] = na[n * LA + j]; }
        else      { g_cidx_v[n * NCV + slot] = j; g_w_v[n * NCV + slot] = na[n * LV + j]; }
    }
    s_red[tid] = ws;
    __syncthreads();
    for (int s = 256; s > 0; s >>= 1) {
        if (tid < s) s_red[tid] += s_red[tid + s];
        __syncthreads();
    }
    if (tid == 0) {
        if (side) g_invS_va[n] = 1.f / s_red[0];
        else      g_invS_av[n] = 1.f / s_red[0];
    }
}

// ---------- kernel 2: round-10 kmain + fused last-block scatter/prune ----------
// grid (H, NB, 2): z==0 -> v side, z==1 -> a side
__global__ void __launch_bounds__(512, 2)
kmain(const float* __restrict__ pos_v_q, const float* __restrict__ pos_v_k,
      const float* __restrict__ pos_a_q, const float* __restrict__ pos_a_k,
      const float* __restrict__ M_av,    const float* __restrict__ M_va,
      const float* __restrict__ spu_a_cls, const float* __restrict__ spu_v_cls,
      const float* __restrict__ n_attn_av, const float* __restrict__ n_attn_va,
      const float* __restrict__ u_v,       const float* __restrict__ u_a,
      float* __restrict__ out) {
    int h = blockIdx.x, n = blockIdx.y, side = blockIdx.z;
    int tid = threadIdx.x;

    __shared__ int   s_idxL[NCV];
    __shared__ float s_wL[NCV];
    __shared__ int   s_offS[NCV];
    __shared__ float s_wS[NCV];
    __shared__ float s_cls[DH];
    __shared__ float s_red[512];
    __shared__ int   s_last;

    int Lcnt, Scnt, Mstride, clsoff;
    const float *kten, *qten, *M, *cls;
    const int *cidxL, *cidxS;
    const float *gwL, *gwS;
    float invS_pos, invS_cls;
    float* acc;
    if (side == 0) {
        Lcnt = NCV; Scnt = NCA; Mstride = LV; clsoff = OFF_VCLS;
        kten = pos_v_k; qten = pos_v_q; M = M_av; cls = spu_a_cls;
        cidxL = g_cidx_v; cidxS = g_cidx_a;
        gwL = g_w_v; gwS = g_w_a;
        invS_pos = g_invS_va[n]; invS_cls = g_invS_av[n];
        acc = g_probv + n * NCV;
    } else {
        Lcnt = NCA; Scnt = NCV; Mstride = LA; clsoff = OFF_ACLS;
        kten = pos_a_k; qten = pos_a_q; M = M_va; cls = spu_v_cls;
        cidxL = g_cidx_a; cidxS = g_cidx_v;
        gwL = g_w_a; gwS = g_w_v;
        invS_pos = g_invS_av[n]; invS_cls = g_invS_va[n];
        acc = g_proba + n * NCA;
    }

    if (tid < Lcnt) {
        s_idxL[tid] = cidxL[n * Lcnt + tid];
        s_wL[tid]   = gwL[n * Lcnt + tid];
    }
    if (tid < Scnt) {
        s_offS[tid] = cidxS[n * Scnt + tid] * Mstride;
        s_wS[tid]   = gwS[n * Scnt + tid];
    }
    if (tid < DH) s_cls[tid] = cls[(n * H + h) * DH + tid];
    __syncthreads();

    const float* kbase = kten + (size_t)(n * H + h) * (side ? LA : LV) * DH;
    const float* Mbase = M + (size_t)(n * H + h) * (size_t)LA * LV;

    if (tid < Lcnt) {
        int il = s_idxL[tid];
        const float4* krow = (const float4*)(kbase + (size_t)il * DH);
        float spu = 0.f;
        #pragma unroll
        for (int d4 = 0; d4 < DH / 4; d4++) {
            float4 v = krow[d4];
            spu = fmaf(v.x, s_cls[4 * d4 + 0], spu);
            spu = fmaf(v.y, s_cls[4 * d4 + 1], spu);
            spu = fmaf(v.z, s_cls[4 * d4 + 2], spu);
            spu = fmaf(v.w, s_cls[4 * d4 + 3], spu);
        }
        spu *= 0.125f;
        float p0 = 0.f, p1 = 0.f, p2 = 0.f, p3 = 0.f;
        for (int a = 0; a < Scnt; a += 4) {
            p0 = fmaf(Mbase[s_offS[a + 0] + il], s_wS[a + 0], p0);
            p1 = fmaf(Mbase[s_offS[a + 1] + il], s_wS[a + 1], p1);
            p2 = fmaf(Mbase[s_offS[a + 2] + il], s_wS[a + 2], p2);
            p3 = fmaf(Mbase[s_offS[a + 3] + il], s_wS[a + 3], p3);
        }
        float posv = ((p0 + p1) + (p2 + p3)) * invS_pos;
        float sig = 1.f / (1.f + __expf(posv - spu));
        atomicAdd(&acc[tid], sig);
    }

    // cls: weighted sum of gathered q rows -> 64 floats, direct store
    const float* qbase = qten + (size_t)(n * H + h) * (side ? LA : LV) * DH;
    {
        int g = tid >> 6, d = tid & 63;
        float a2 = 0.f;
        for (int l = g; l < Lcnt; l += 8)
            a2 = fmaf(qbase[(size_t)s_idxL[l] * DH + d], s_wL[l], a2);
        s_red[tid] = a2;
        __syncthreads();
        if (tid < DH) {
            float t = 0.f;
            #pragma unroll
            for (int gg = 0; gg < 8; gg++) t += s_red[gg * 64 + tid];
            out[(size_t)n * ROW + clsoff + h * DH + tid] = t * invS_cls;
        }
    }

    // ---- fused finalization: last block of this (n,side) scatters + prunes ----
    __syncthreads();
    if (tid == 0) {
        __threadfence();
        int t = atomicAdd(&g_cnt[n * 2 + side], 1);
        s_last = (t == H - 1);
    }
    __syncthreads();
    if (!s_last) return;

    float* row = out + (size_t)n * ROW;
    if (side == 0) {
        if (tid < NCV) {
            int pos = s_idxL[tid];                       // sorted id == scatter target
            float p = g_probv[n * NCV + tid] * (1.f / 12.f);
            row[OFF_PROBV + pos] = p;
            row[OFF_PRAV + pos]  = (u_v[n * LV + pos] < p) ? 0.f : n_attn_av[n * LV + pos];
        }
    } else {
        if (tid < NCA) {
            int pos = s_idxL[tid];
            float p = g_proba[n * NCA + tid] * (1.f / 12.f);
            row[OFF_PROBA + pos] = p;
            row[OFF_PRVA + pos]  = (u_a[n * LA + pos] < p) ? 0.f : n_attn_va[n * LA + pos];
        }
    }
}

extern "C" void kernel_launch(void* const* d_in, const int* in_sizes, int n_in,
                              void* d_out, int out_size) {
    const float* pos_v_q   = (const float*)d_in[0];
    const float* pos_v_k   = (const float*)d_in[1];
    const float* pos_a_q   = (const float*)d_in[2];
    const float* pos_a_k   = (const float*)d_in[3];
    const float* M_av      = (const float*)d_in[4];
    const float* M_va      = (const float*)d_in[5];
    const float* n_attn_av = (const float*)d_in[6];
    const float* n_attn_va = (const float*)d_in[7];
    const float* spu_a_cls = (const float*)d_in[8];
    const float* spu_v_cls = (const float*)d_in[9];
    const float* u_v       = (const float*)d_in[10];
    const float* u_a       = (const float*)d_in[11];
    const int*   ids_v     = (const int*)d_in[12];
    const int*   ids_a     = (const int*)d_in[13];
    float* out = (float*)d_out;

    kprep<<<dim3(NB, 4), 512>>>(n_attn_av, n_attn_va, ids_v, ids_a, out);
    kmain<<<dim3(H, NB, 2), 512>>>(pos_v_q, pos_v_k, pos_a_q, pos_a_k,
                                   M_av, M_va, spu_a_cls, spu_v_cls,
                                   n_attn_av, n_attn_va, u_v, u_a, out);
}